// round 2
// baseline (speedup 1.0000x reference)
#include <cuda_runtime.h>
#include <math.h>

#define NN 100000
#define EE 3200000
#define FF 128
#define UU 1000

// Scratch
__device__ float g_XW[(long long)NN * FF];
__device__ float g_AGG[(long long)NN * FF];
__device__ float g_H[(long long)NN * FF];
__device__ float g_inv[NN];
__device__ int   g_deg[NN];
__device__ int   g_mask[NN];
__device__ int   g_list[NN];
__device__ int   g_cnt;
__device__ int   g_is32;   // 1 if edge_index stored as int32

__device__ __forceinline__ int edge_at(const void* p, long long i) {
    return g_is32 ? ((const int*)p)[i] : (int)((const long long*)p)[i];
}

// ---------------------------------------------------------------------------
__global__ void k_init() {
    int idx = blockIdx.x * 256 + threadIdx.x;   // grid covers NN*FF
    g_AGG[idx] = 0.0f;
    if (idx < NN) { g_deg[idx] = 0; g_mask[idx] = (idx < UU) ? 1 : 0; }
    if (idx == 0) { g_cnt = 0; g_is32 = 0; }
}

// dtype detect: if true int64 (values < 2^31), every odd 32-bit word is 0.
__global__ void k_detect(const int* __restrict__ e32) {
    int e = blockIdx.x * 256 + threadIdx.x;
    if (e < EE && e32[2 * e + 1] != 0) g_is32 = 1;
}

__global__ void k_deg_mask(const void* __restrict__ eS, const void* __restrict__ eD,
                           long long dOff) {
    int e = blockIdx.x * 256 + threadIdx.x;
    if (e >= EE) return;
    int src = edge_at(eS, e);
    int dst = edge_at(eD, dOff + e);
    if ((unsigned)src >= NN || (unsigned)dst >= NN) return;
    atomicAdd(&g_deg[dst], 1);
    if (dst < UU) g_mask[src] = 1;
}

__global__ void k_invsqrt() {
    int i = blockIdx.x * 256 + threadIdx.x;
    if (i < NN) g_inv[i] = rsqrtf((float)g_deg[i] + 1.0f);
}

__global__ void k_compact() {
    int i = blockIdx.x * 256 + threadIdx.x;
    if (i < NN && g_mask[i]) {
        int p = atomicAdd(&g_cnt, 1);
        g_list[p] = i;
    }
}

// ---------------------------------------------------------------------------
// GEMM: 64 rows x 128 cols per block, 256 threads, K chunked by 32.
// Static shared only (~26KB). Thread (tx=tid&15, ty=tid>>4) computes rows
// 4*ty..4*ty+3 and cols {tx*4+q + 64*j2}.
__global__ void k_gemm(const float* __restrict__ X0, const float* __restrict__ W,
                       int useList) {
    __shared__ float Ws[32 * 128];     // W[kc..kc+31][0..127]
    __shared__ float XsT[32 * 68];     // X chunk transposed [k][row], pad 68
    __shared__ int   rlist[64];
    __shared__ int   s_n;

    int tid = threadIdx.x;
    if (tid == 0) s_n = useList ? g_cnt : NN;
    __syncthreads();
    int n = s_n;
    int base = blockIdx.x * 64;
    if (base >= n) return;

    if (tid < 64) {
        int gr = base + tid;
        rlist[tid] = (gr < n) ? (useList ? g_list[gr] : gr) : -1;
    }
    const float* X = useList ? g_H : X0;

    int tx = tid & 15, ty = tid >> 4;
    float acc[4][8];
    #pragma unroll
    for (int i = 0; i < 4; i++)
        #pragma unroll
        for (int j = 0; j < 8; j++) acc[i][j] = 0.0f;
    __syncthreads();

    for (int kc = 0; kc < 128; kc += 32) {
        #pragma unroll 4
        for (int idx = tid; idx < 4096; idx += 256)
            Ws[idx] = W[(kc + (idx >> 7)) * 128 + (idx & 127)];
        #pragma unroll 4
        for (int idx = tid; idx < 2048; idx += 256) {
            int r = idx >> 5, c = idx & 31;
            int grow = rlist[r];
            XsT[c * 68 + r] = (grow >= 0) ? X[(long long)grow * FF + kc + c] : 0.0f;
        }
        __syncthreads();

        #pragma unroll
        for (int k = 0; k < 32; k++) {
            float4 a = *(const float4*)&XsT[k * 68 + ty * 4];
            float4 b0 = *(const float4*)&Ws[k * 128 + tx * 4];
            float4 b1 = *(const float4*)&Ws[k * 128 + 64 + tx * 4];
            float av[4] = {a.x, a.y, a.z, a.w};
            float bv[8] = {b0.x, b0.y, b0.z, b0.w, b1.x, b1.y, b1.z, b1.w};
            #pragma unroll
            for (int i = 0; i < 4; i++)
                #pragma unroll
                for (int j = 0; j < 8; j++) acc[i][j] += av[i] * bv[j];
        }
        __syncthreads();
    }

    #pragma unroll
    for (int i = 0; i < 4; i++) {
        int gr = base + ty * 4 + i;
        if (gr < n) {
            int grow = rlist[ty * 4 + i];
            float* o = g_XW + (long long)grow * FF;
            *(float4*)&o[tx * 4]      = *(float4*)&acc[i][0];
            *(float4*)&o[64 + tx * 4] = *(float4*)&acc[i][4];
        }
    }
}

// ---------------------------------------------------------------------------
// Edge scatter: one warp per edge. mode 0: keep iff g_mask[dst];
// mode 1: keep iff dst < U.
__global__ void k_scatter(const void* __restrict__ eS, const void* __restrict__ eD,
                          long long dOff, int mode) {
    int gt = blockIdx.x * 256 + threadIdx.x;
    int e = gt >> 5;
    int lane = threadIdx.x & 31;
    if (e >= EE) return;
    int src = edge_at(eS, e);
    int dst = edge_at(eD, dOff + e);
    if ((unsigned)src >= NN || (unsigned)dst >= NN) return;
    if (mode == 0) { if (!g_mask[dst]) return; }
    else           { if (dst >= UU)    return; }
    float coef = g_inv[src] * g_inv[dst];
    float4 v = ((const float4*)(g_XW + (long long)src * FF))[lane];
    float* a = g_AGG + (long long)dst * FF + lane * 4;
    atomicAdd(a + 0, v.x * coef);
    atomicAdd(a + 1, v.y * coef);
    atomicAdd(a + 2, v.z * coef);
    atomicAdd(a + 3, v.w * coef);
}

// ---------------------------------------------------------------------------
__global__ void k_combine(const float* __restrict__ bias, float* __restrict__ outp,
                          int layer) {
    int idx = blockIdx.x;
    int row;
    float* out;
    if (layer == 1) {
        if (idx >= g_cnt) return;
        row = g_list[idx];
        out = g_H;
    } else {
        row = idx;       // grid = UU
        out = outp;
    }
    int t = threadIdx.x; // 128
    float s = g_inv[row]; s = s * s;
    long long o = (long long)row * FF + t;
    float v = g_AGG[o] + g_XW[o] * s + __ldg(&bias[t]);
    out[o] = (v > 0.0f) ? v : expm1f(v);
}

__global__ void k_zero_head() {
    int idx = blockIdx.x * 256 + threadIdx.x;  // UU*FF
    g_AGG[idx] = 0.0f;
}

__global__ void k_copy_tail(const float* __restrict__ x, float* __restrict__ out) {
    long long idx = (long long)blockIdx.x * 256 + threadIdx.x;  // (NN-UU)*FF
    long long o = (long long)UU * FF + idx;
    out[o] = x[o];
}

// ---------------------------------------------------------------------------
extern "C" void kernel_launch(void* const* d_in, const int* in_sizes, int n_in,
                              void* d_out, int out_size) {
    const float *x = 0, *W1 = 0, *b1 = 0, *W2 = 0, *b2 = 0;
    const void *eA = 0, *eB = 0;
    long long dOff = 0;
    for (int i = 0; i < n_in; i++) {
        long long s = in_sizes[i];
        if (s == (long long)NN * FF)      x = (const float*)d_in[i];
        else if (s == 2LL * EE)           eA = d_in[i];
        else if (s == (long long)EE)     { if (!eA) eA = d_in[i]; else eB = d_in[i]; }
        else if (s == FF * FF)           { if (!W1) W1 = (const float*)d_in[i];
                                           else     W2 = (const float*)d_in[i]; }
        else if (s == FF)                { if (!b1) b1 = (const float*)d_in[i];
                                           else     b2 = (const float*)d_in[i]; }
    }
    if (!eB) { eB = eA; dOff = EE; }   // combined [2,E] layout
    float* out = (float*)d_out;

    // setup
    k_init<<<(NN * FF) / 256, 256>>>();
    k_detect<<<(EE + 255) / 256, 256>>>((const int*)eA);
    k_deg_mask<<<(EE + 255) / 256, 256>>>(eA, eB, dOff);
    k_invsqrt<<<(NN + 255) / 256, 256>>>();
    k_compact<<<(NN + 255) / 256, 256>>>();

    const int gemm_grid = (NN + 63) / 64;
    const long long scat_threads = (long long)EE * 32;
    const int scat_grid = (int)((scat_threads + 255) / 256);

    // layer 1
    k_gemm<<<gemm_grid, 256>>>(x, W1, 0);
    k_scatter<<<scat_grid, 256>>>(eA, eB, dOff, 0);
    k_combine<<<NN, 128>>>(b1, 0, 1);

    // layer 2
    k_gemm<<<gemm_grid, 256>>>(x, W2, 1);
    k_zero_head<<<(UU * FF) / 256, 256>>>();
    k_scatter<<<scat_grid, 256>>>(eA, eB, dOff, 1);
    k_combine<<<UU, 128>>>(b2, out, 2);

    // passthrough rows [U, N)
    k_copy_tail<<<((NN - UU) * FF) / 256, 256>>>(x, out);
}

// round 6
// speedup vs baseline: 3.8919x; 3.8919x over previous
#include <cuda_runtime.h>
#include <math.h>

#define NN 100000
#define EE 3200000
#define FF 128
#define UU 1000

// Scratch (device globals) — referenced ONLY inside kernels (never as launch args!)
__device__ float g_A  [(long long)NN * FF];  // aggregation buffer
__device__ float g_H  [(long long)NN * FF];  // layer-1 activations
__device__ float g_inv[NN];
__device__ int   g_deg[NN];
__device__ int   g_mask[NN];
__device__ int   g_list[NN];    // compact idx -> node (GEMM work list)
__device__ int   g_off[NN];     // bucket start (atomic-allocated, unordered)
__device__ int   g_cur[NN];
__device__ int   g_csr[EE];
__device__ int   g_cnt;
__device__ int   g_total;
__device__ int   g_is32;

__device__ __forceinline__ int edge_at(const void* p, long long i) {
    return g_is32 ? ((const int*)p)[i] : (int)((const long long*)p)[i];
}

// ---------------------------------------------------------------------------
__global__ void k_init() {
    int i = blockIdx.x * 256 + threadIdx.x;
    if (i < NN) {
        g_deg[i] = 0; g_cur[i] = 0;
        g_mask[i] = (i < UU) ? 1 : 0;
    }
    if (i == 0) { g_cnt = 0; g_total = 0; g_is32 = 0; }
}

__global__ void k_detect(const int* __restrict__ e32) {
    int e = blockIdx.x * 256 + threadIdx.x;
    if (e < EE && e32[2 * e + 1] != 0) g_is32 = 1;
}

__global__ void k_deg_mask(const void* __restrict__ eS, const void* __restrict__ eD,
                           long long dOff) {
    int e = blockIdx.x * 256 + threadIdx.x;
    if (e >= EE) return;
    int src = edge_at(eS, e);
    int dst = edge_at(eD, dOff + e);
    if ((unsigned)src >= NN || (unsigned)dst >= NN) return;
    atomicAdd(&g_deg[dst], 1);
    if (dst < UU) g_mask[src] = 1;
}

__global__ void k_inv_compact() {
    int i = blockIdx.x * 256 + threadIdx.x;
    if (i >= NN) return;
    g_inv[i] = rsqrtf((float)g_deg[i] + 1.0f);
    if (g_mask[i]) {
        int p = atomicAdd(&g_cnt, 1);
        g_list[p] = i;
    }
}

// Scan-free bucket allocation: bucket ORDER is irrelevant, only disjointness
// and per-node contiguity matter.
__global__ void k_alloc_off() {
    int i = blockIdx.x * 256 + threadIdx.x;
    if (i < NN) g_off[i] = atomicAdd(&g_total, g_deg[i]);
}

__global__ void k_fill(const void* __restrict__ eS, const void* __restrict__ eD,
                       long long dOff) {
    int e = blockIdx.x * 256 + threadIdx.x;
    if (e >= EE) return;
    int src = edge_at(eS, e);
    int dst = edge_at(eD, dOff + e);
    if ((unsigned)src >= NN || (unsigned)dst >= NN) return;
    int pos = g_off[dst] + atomicAdd(&g_cur[dst], 1);
    if ((unsigned)pos < EE) g_csr[pos] = src;
}

// ---------------------------------------------------------------------------
// Layer-1 aggregation: warp per compact row; writes g_A[node].
__global__ void k_agg1(const float* __restrict__ x) {
    int w = (blockIdx.x * 256 + threadIdx.x) >> 5;
    int lane = threadIdx.x & 31;
    if (w >= g_cnt) return;
    int row = g_list[w];
    float invr = g_inv[row];
    float4 acc = ((const float4*)(x + (long long)row * FF))[lane];
    float s = invr * invr;
    acc.x *= s; acc.y *= s; acc.z *= s; acc.w *= s;
    int beg = g_off[row], end = beg + g_deg[row];
    for (int j = beg; j < end; j++) {
        int src = g_csr[j];
        float c = g_inv[src] * invr;
        float4 v = ((const float4*)(x + (long long)src * FF))[lane];
        acc.x += c * v.x; acc.y += c * v.y; acc.z += c * v.z; acc.w += c * v.w;
    }
    ((float4*)(g_A + (long long)row * FF))[lane] = acc;
}

// Layer-2 aggregation: warp per dst row < UU; reads g_H by symbol.
__global__ void k_agg2() {
    int w = (blockIdx.x * 256 + threadIdx.x) >> 5;
    int lane = threadIdx.x & 31;
    if (w >= UU) return;
    int row = w;
    float invr = g_inv[row];
    float4 acc = ((const float4*)(g_H + (long long)row * FF))[lane];
    float s = invr * invr;
    acc.x *= s; acc.y *= s; acc.z *= s; acc.w *= s;
    int beg = g_off[row], end = beg + g_deg[row];
    for (int j = beg; j < end; j++) {
        int src = g_csr[j];
        float c = g_inv[src] * invr;
        float4 v = ((const float4*)(g_H + (long long)src * FF))[lane];
        acc.x += c * v.x; acc.y += c * v.y; acc.z += c * v.z; acc.w += c * v.w;
    }
    ((float4*)(g_A + (long long)row * FF))[lane] = acc;
}

// ---------------------------------------------------------------------------
// Fused GEMM + bias + ELU, reading g_A by SYMBOL.
// layer=1: rows = g_list[0..g_cnt), write g_H (symbol).
// layer=2: rows = [0, UU), write outp (harness pointer).
__global__ void k_gemm_fused(const float* __restrict__ W, const float* __restrict__ bias,
                             float* __restrict__ outp, int layer) {
    __shared__ float Ws[32 * 128];
    __shared__ float XsT[32 * 68];
    __shared__ int   rlist[64];
    __shared__ int   s_n;

    int tid = threadIdx.x;
    if (tid == 0) s_n = (layer == 1) ? g_cnt : UU;
    __syncthreads();
    int n = s_n;
    int base = blockIdx.x * 64;
    if (base >= n) return;

    if (tid < 64) {
        int gr = base + tid;
        rlist[tid] = (gr < n) ? ((layer == 1) ? g_list[gr] : gr) : -1;
    }
    float* O = (layer == 1) ? g_H : outp;

    int tx = tid & 15, ty = tid >> 4;
    float acc[4][8];
    #pragma unroll
    for (int i = 0; i < 4; i++)
        #pragma unroll
        for (int j = 0; j < 8; j++) acc[i][j] = 0.0f;
    __syncthreads();

    for (int kc = 0; kc < 128; kc += 32) {
        #pragma unroll 4
        for (int idx = tid; idx < 4096; idx += 256)
            Ws[idx] = W[(kc + (idx >> 7)) * 128 + (idx & 127)];
        #pragma unroll 4
        for (int idx = tid; idx < 2048; idx += 256) {
            int r = idx >> 5, c = idx & 31;
            int grow = rlist[r];
            XsT[c * 68 + r] = (grow >= 0) ? g_A[(long long)grow * FF + kc + c] : 0.0f;
        }
        __syncthreads();

        #pragma unroll
        for (int k = 0; k < 32; k++) {
            float4 a  = *(const float4*)&XsT[k * 68 + ty * 4];
            float4 b0 = *(const float4*)&Ws[k * 128 + tx * 4];
            float4 b1 = *(const float4*)&Ws[k * 128 + 64 + tx * 4];
            float av[4] = {a.x, a.y, a.z, a.w};
            float bv[8] = {b0.x, b0.y, b0.z, b0.w, b1.x, b1.y, b1.z, b1.w};
            #pragma unroll
            for (int i = 0; i < 4; i++)
                #pragma unroll
                for (int j = 0; j < 8; j++) acc[i][j] += av[i] * bv[j];
        }
        __syncthreads();
    }

    float bj[8];
    #pragma unroll
    for (int q = 0; q < 4; q++) {
        bj[q]     = __ldg(&bias[tx * 4 + q]);
        bj[4 + q] = __ldg(&bias[64 + tx * 4 + q]);
    }

    #pragma unroll
    for (int i = 0; i < 4; i++) {
        int gr = base + ty * 4 + i;
        if (gr < n) {
            int grow = rlist[ty * 4 + i];
            float* o = O + (long long)grow * FF;
            float r0[4], r1[4];
            #pragma unroll
            for (int q = 0; q < 4; q++) {
                float v = acc[i][q] + bj[q];
                r0[q] = (v > 0.0f) ? v : expm1f(v);
                v = acc[i][4 + q] + bj[4 + q];
                r1[q] = (v > 0.0f) ? v : expm1f(v);
            }
            *(float4*)&o[tx * 4]      = *(float4*)&r0[0];
            *(float4*)&o[64 + tx * 4] = *(float4*)&r1[0];
        }
    }
}

__global__ void k_copy_tail(const float* __restrict__ x, float* __restrict__ out) {
    long long idx = (long long)blockIdx.x * 256 + threadIdx.x;  // (NN-UU)*FF/4
    long long o = (long long)UU * FF / 4 + idx;
    ((float4*)out)[o] = ((const float4*)x)[o];
}

// ---------------------------------------------------------------------------
extern "C" void kernel_launch(void* const* d_in, const int* in_sizes, int n_in,
                              void* d_out, int out_size) {
    const float *x = 0, *W1 = 0, *b1 = 0, *W2 = 0, *b2 = 0;
    const void *eA = 0, *eB = 0;
    long long dOff = 0;
    for (int i = 0; i < n_in; i++) {
        long long s = in_sizes[i];
        if (s == (long long)NN * FF)      x = (const float*)d_in[i];
        else if (s == 2LL * EE)           eA = d_in[i];
        else if (s == (long long)EE)     { if (!eA) eA = d_in[i]; else eB = d_in[i]; }
        else if (s == FF * FF)           { if (!W1) W1 = (const float*)d_in[i];
                                           else     W2 = (const float*)d_in[i]; }
        else if (s == FF)                { if (!b1) b1 = (const float*)d_in[i];
                                           else     b2 = (const float*)d_in[i]; }
    }
    if (!eB) { eB = eA; dOff = EE; }
    float* out = (float*)d_out;

    const int egrid = (EE + 255) / 256;
    const int ngrid = (NN + 255) / 256;

    // setup + CSR (scan-free)
    k_init<<<ngrid, 256>>>();
    k_detect<<<egrid, 256>>>((const int*)eA);
    k_deg_mask<<<egrid, 256>>>(eA, eB, dOff);
    k_inv_compact<<<ngrid, 256>>>();
    k_alloc_off<<<ngrid, 256>>>();
    k_fill<<<egrid, 256>>>(eA, eB, dOff);

    // layer 1: gather-aggregate x over S, fused GEMM+bias+ELU -> g_H
    k_agg1<<<(NN * 32 + 255) / 256, 256>>>(x);
    k_gemm_fused<<<(NN + 63) / 64, 256>>>(W1, b1, out, 1);

    // layer 2: gather-aggregate h over [0,UU), fused GEMM -> out head
    k_agg2<<<(UU * 32 + 255) / 256, 256>>>();
    k_gemm_fused<<<(UU + 63) / 64, 256>>>(W2, b2, out, 2);

    // passthrough rows [U, N)
    k_copy_tail<<<((NN - UU) * FF / 4 + 255) / 256, 256>>>(x, out);
}

// round 7
// speedup vs baseline: 5.0573x; 1.2994x over previous
#include <cuda_runtime.h>
#include <math.h>

#define NN 100000
#define EE 3200000
#define FF 128
#define UU 1000

// Scratch (device globals) — referenced ONLY inside kernels (never as launch args!)
__device__ float g_A  [(long long)NN * FF];  // aggregation buffer
__device__ float g_H  [(long long)NN * FF];  // layer-1 activations
__device__ float g_inv[NN];
__device__ int   g_deg[NN];
__device__ int   g_mask[NN];
__device__ int   g_list[NN];    // compact idx -> node (GEMM work list)
__device__ int   g_off[NN];     // bucket start (atomic-allocated, masked only)
__device__ int   g_cur[NN];
__device__ int   g_csr[EE];
__device__ int   g_cnt;
__device__ int   g_total;
__device__ int   g_is32;

__device__ __forceinline__ int edge_at(const void* p, long long i) {
    return g_is32 ? ((const int*)p)[i] : (int)((const long long*)p)[i];
}

// ---------------------------------------------------------------------------
__global__ void k_init() {
    int i = blockIdx.x * 256 + threadIdx.x;
    if (i < NN) {
        g_deg[i] = 0; g_cur[i] = 0;
        g_mask[i] = (i < UU) ? 1 : 0;
    }
    if (i == 0) { g_cnt = 0; g_total = 0; g_is32 = 0; }
}

// dtype detect on a 256K-element prefix (odd 32-bit words all zero <=> int64)
#define DETECT_N 262144
__global__ void k_detect(const int* __restrict__ e32) {
    int e = blockIdx.x * 256 + threadIdx.x;
    if (e < DETECT_N && e32[2 * e + 1] != 0) g_is32 = 1;
}

__global__ void k_deg_mask(const void* __restrict__ eS, const void* __restrict__ eD,
                           long long dOff) {
    int e = blockIdx.x * 256 + threadIdx.x;
    if (e >= EE) return;
    int src = edge_at(eS, e);
    int dst = edge_at(eD, dOff + e);
    if ((unsigned)src >= NN || (unsigned)dst >= NN) return;
    atomicAdd(&g_deg[dst], 1);
    if (dst < UU) g_mask[src] = 1;
}

// inv-sqrt + compact list + scan-free bucket allocation (masked rows only)
__global__ void k_inv_compact() {
    int i = blockIdx.x * 256 + threadIdx.x;
    if (i >= NN) return;
    int d = g_deg[i];
    g_inv[i] = rsqrtf((float)d + 1.0f);
    if (g_mask[i]) {
        int p = atomicAdd(&g_cnt, 1);
        g_list[p] = i;
        g_off[i] = atomicAdd(&g_total, d);
    }
}

// fill only buckets whose dst is in S (~1/3 of edges)
__global__ void k_fill(const void* __restrict__ eS, const void* __restrict__ eD,
                       long long dOff) {
    int e = blockIdx.x * 256 + threadIdx.x;
    if (e >= EE) return;
    int dst = edge_at(eD, dOff + e);
    if ((unsigned)dst >= NN || !g_mask[dst]) return;
    int src = edge_at(eS, e);
    if ((unsigned)src >= NN) return;
    int pos = g_off[dst] + atomicAdd(&g_cur[dst], 1);
    if ((unsigned)pos < EE) g_csr[pos] = src;
}

// ---------------------------------------------------------------------------
// Layer-1 aggregation: warp per compact row; edge loop unrolled x4 for MLP.
__global__ void k_agg1(const float* __restrict__ x) {
    int w = (blockIdx.x * 256 + threadIdx.x) >> 5;
    int lane = threadIdx.x & 31;
    if (w >= g_cnt) return;
    int row = g_list[w];
    float invr = g_inv[row];
    float4 acc = ((const float4*)(x + (long long)row * FF))[lane];
    float s = invr * invr;
    acc.x *= s; acc.y *= s; acc.z *= s; acc.w *= s;
    int beg = g_off[row], end = beg + g_deg[row];
    int j = beg;
    for (; j + 4 <= end; j += 4) {
        int s0 = g_csr[j], s1 = g_csr[j + 1], s2 = g_csr[j + 2], s3 = g_csr[j + 3];
        float c0 = g_inv[s0] * invr, c1 = g_inv[s1] * invr;
        float c2 = g_inv[s2] * invr, c3 = g_inv[s3] * invr;
        float4 v0 = ((const float4*)(x + (long long)s0 * FF))[lane];
        float4 v1 = ((const float4*)(x + (long long)s1 * FF))[lane];
        float4 v2 = ((const float4*)(x + (long long)s2 * FF))[lane];
        float4 v3 = ((const float4*)(x + (long long)s3 * FF))[lane];
        acc.x += c0 * v0.x + c1 * v1.x + c2 * v2.x + c3 * v3.x;
        acc.y += c0 * v0.y + c1 * v1.y + c2 * v2.y + c3 * v3.y;
        acc.z += c0 * v0.z + c1 * v1.z + c2 * v2.z + c3 * v3.z;
        acc.w += c0 * v0.w + c1 * v1.w + c2 * v2.w + c3 * v3.w;
    }
    for (; j < end; j++) {
        int src = g_csr[j];
        float c = g_inv[src] * invr;
        float4 v = ((const float4*)(x + (long long)src * FF))[lane];
        acc.x += c * v.x; acc.y += c * v.y; acc.z += c * v.z; acc.w += c * v.w;
    }
    ((float4*)(g_A + (long long)row * FF))[lane] = acc;
}

// Layer-2 aggregation: warp per dst row < UU.
__global__ void k_agg2() {
    int w = (blockIdx.x * 256 + threadIdx.x) >> 5;
    int lane = threadIdx.x & 31;
    if (w >= UU) return;
    int row = w;
    float invr = g_inv[row];
    float4 acc = ((const float4*)(g_H + (long long)row * FF))[lane];
    float s = invr * invr;
    acc.x *= s; acc.y *= s; acc.z *= s; acc.w *= s;
    int beg = g_off[row], end = beg + g_deg[row];
    int j = beg;
    for (; j + 2 <= end; j += 2) {
        int s0 = g_csr[j], s1 = g_csr[j + 1];
        float c0 = g_inv[s0] * invr, c1 = g_inv[s1] * invr;
        float4 v0 = ((const float4*)(g_H + (long long)s0 * FF))[lane];
        float4 v1 = ((const float4*)(g_H + (long long)s1 * FF))[lane];
        acc.x += c0 * v0.x + c1 * v1.x;
        acc.y += c0 * v0.y + c1 * v1.y;
        acc.z += c0 * v0.z + c1 * v1.z;
        acc.w += c0 * v0.w + c1 * v1.w;
    }
    for (; j < end; j++) {
        int src = g_csr[j];
        float c = g_inv[src] * invr;
        float4 v = ((const float4*)(g_H + (long long)src * FF))[lane];
        acc.x += c * v.x; acc.y += c * v.y; acc.z += c * v.z; acc.w += c * v.w;
    }
    ((float4*)(g_A + (long long)row * FF))[lane] = acc;
}

// ---------------------------------------------------------------------------
// Fused GEMM + bias + ELU, reading g_A by SYMBOL.
// layer=1: rows = g_list[0..g_cnt), write g_H. layer=2: rows [0,UU), write outp.
__global__ void k_gemm_fused(const float* __restrict__ W, const float* __restrict__ bias,
                             float* __restrict__ outp, int layer) {
    __shared__ float Ws[32 * 128];
    __shared__ float XsT[32 * 68];
    __shared__ int   rlist[64];
    __shared__ int   s_n;

    int tid = threadIdx.x;
    if (tid == 0) s_n = (layer == 1) ? g_cnt : UU;
    __syncthreads();
    int n = s_n;
    int base = blockIdx.x * 64;
    if (base >= n) return;

    if (tid < 64) {
        int gr = base + tid;
        rlist[tid] = (gr < n) ? ((layer == 1) ? g_list[gr] : gr) : -1;
    }
    float* O = (layer == 1) ? g_H : outp;

    int tx = tid & 15, ty = tid >> 4;
    float acc[4][8];
    #pragma unroll
    for (int i = 0; i < 4; i++)
        #pragma unroll
        for (int j = 0; j < 8; j++) acc[i][j] = 0.0f;
    __syncthreads();

    for (int kc = 0; kc < 128; kc += 32) {
        #pragma unroll 4
        for (int idx = tid; idx < 4096; idx += 256)
            Ws[idx] = W[(kc + (idx >> 7)) * 128 + (idx & 127)];
        #pragma unroll 4
        for (int idx = tid; idx < 2048; idx += 256) {
            int r = idx >> 5, c = idx & 31;
            int grow = rlist[r];
            XsT[c * 68 + r] = (grow >= 0) ? g_A[(long long)grow * FF + kc + c] : 0.0f;
        }
        __syncthreads();

        #pragma unroll
        for (int k = 0; k < 32; k++) {
            float4 a  = *(const float4*)&XsT[k * 68 + ty * 4];
            float4 b0 = *(const float4*)&Ws[k * 128 + tx * 4];
            float4 b1 = *(const float4*)&Ws[k * 128 + 64 + tx * 4];
            float av[4] = {a.x, a.y, a.z, a.w};
            float bv[8] = {b0.x, b0.y, b0.z, b0.w, b1.x, b1.y, b1.z, b1.w};
            #pragma unroll
            for (int i = 0; i < 4; i++)
                #pragma unroll
                for (int j = 0; j < 8; j++) acc[i][j] += av[i] * bv[j];
        }
        __syncthreads();
    }

    float bj[8];
    #pragma unroll
    for (int q = 0; q < 4; q++) {
        bj[q]     = __ldg(&bias[tx * 4 + q]);
        bj[4 + q] = __ldg(&bias[64 + tx * 4 + q]);
    }

    #pragma unroll
    for (int i = 0; i < 4; i++) {
        int gr = base + ty * 4 + i;
        if (gr < n) {
            int grow = rlist[ty * 4 + i];
            float* o = O + (long long)grow * FF;
            float r0[4], r1[4];
            #pragma unroll
            for (int q = 0; q < 4; q++) {
                float v = acc[i][q] + bj[q];
                r0[q] = (v > 0.0f) ? v : expm1f(v);
                v = acc[i][4 + q] + bj[4 + q];
                r1[q] = (v > 0.0f) ? v : expm1f(v);
            }
            *(float4*)&o[tx * 4]      = *(float4*)&r0[0];
            *(float4*)&o[64 + tx * 4] = *(float4*)&r1[0];
        }
    }
}

__global__ void k_copy_tail(const float* __restrict__ x, float* __restrict__ out) {
    long long idx = (long long)blockIdx.x * 256 + threadIdx.x;  // (NN-UU)*FF/4
    long long o = (long long)UU * FF / 4 + idx;
    ((float4*)out)[o] = ((const float4*)x)[o];
}

// ---------------------------------------------------------------------------
extern "C" void kernel_launch(void* const* d_in, const int* in_sizes, int n_in,
                              void* d_out, int out_size) {
    const float *x = 0, *W1 = 0, *b1 = 0, *W2 = 0, *b2 = 0;
    const void *eA = 0, *eB = 0;
    long long dOff = 0;
    for (int i = 0; i < n_in; i++) {
        long long s = in_sizes[i];
        if (s == (long long)NN * FF)      x = (const float*)d_in[i];
        else if (s == 2LL * EE)           eA = d_in[i];
        else if (s == (long long)EE)     { if (!eA) eA = d_in[i]; else eB = d_in[i]; }
        else if (s == FF * FF)           { if (!W1) W1 = (const float*)d_in[i];
                                           else     W2 = (const float*)d_in[i]; }
        else if (s == FF)                { if (!b1) b1 = (const float*)d_in[i];
                                           else     b2 = (const float*)d_in[i]; }
    }
    if (!eB) { eB = eA; dOff = EE; }
    float* out = (float*)d_out;

    const int egrid = (EE + 255) / 256;
    const int ngrid = (NN + 255) / 256;

    // setup + CSR (scan-free, masked buckets only)
    k_init<<<ngrid, 256>>>();
    k_detect<<<DETECT_N / 256, 256>>>((const int*)eA);
    k_deg_mask<<<egrid, 256>>>(eA, eB, dOff);
    k_inv_compact<<<ngrid, 256>>>();
    k_fill<<<egrid, 256>>>(eA, eB, dOff);

    // layer 1: gather-aggregate x over S, fused GEMM+bias+ELU -> g_H
    k_agg1<<<(NN * 32 + 255) / 256, 256>>>(x);
    k_gemm_fused<<<(NN + 63) / 64, 256>>>(W1, b1, out, 1);

    // layer 2: gather-aggregate h over [0,UU), fused GEMM -> out head
    k_agg2<<<(UU * 32 + 255) / 256, 256>>>();
    k_gemm_fused<<<(UU + 63) / 64, 256>>>(W2, b2, out, 2);

    // passthrough rows [U, N)
    k_copy_tail<<<((NN - UU) * FF / 4 + 255) / 256, 256>>>(x, out);
}

// round 8
// speedup vs baseline: 5.3108x; 1.0501x over previous
#include <cuda_runtime.h>
#include <cuda_bf16.h>
#include <math.h>

#define NN 100000
#define EE 3200000
#define FF 128
#define UU 1000
#define DETECT_N 262144

// Scratch (device globals) — referenced ONLY inside kernels (never as launch args!)
__device__ float          g_A  [(long long)NN * FF];  // aggregation buffer
__device__ float          g_H  [(long long)NN * FF];  // layer-1 activations
__device__ __nv_bfloat16  g_Xh [(long long)NN * FF];  // bf16 copy of x (gather feed)
__device__ float g_inv[NN];
__device__ int   g_deg[NN];
__device__ int   g_mask[NN];
__device__ int   g_list[NN];
__device__ int   g_off[NN];
__device__ int   g_cur[NN];
__device__ int   g_csr[EE];
__device__ int   g_cnt;
__device__ int   g_total;
__device__ int   g_is32;

__device__ __forceinline__ int edge_at(const void* p, long long i) {
    return g_is32 ? ((const int*)p)[i] : (int)((const long long*)p)[i];
}

// ---------------------------------------------------------------------------
// init + dtype detect fused. grid = 1024 blocks x 256 (covers DETECT_N).
__global__ void k_init(const int* __restrict__ e32) {
    int i = blockIdx.x * 256 + threadIdx.x;
    if (i < NN) {
        g_deg[i] = 0; g_cur[i] = 0;
        g_mask[i] = (i < UU) ? 1 : 0;
    }
    if (i == 0) { g_cnt = 0; g_total = 0; g_is32 = 0; }
    if (i < DETECT_N && e32[2 * i + 1] != 0) g_is32 = 1;
}

__global__ void k_deg_mask(const void* __restrict__ eS, const void* __restrict__ eD,
                           long long dOff) {
    int e = blockIdx.x * 256 + threadIdx.x;
    if (e >= EE) return;
    int src = edge_at(eS, e);
    int dst = edge_at(eD, dOff + e);
    if ((unsigned)src >= NN || (unsigned)dst >= NN) return;
    atomicAdd(&g_deg[dst], 1);
    if (dst < UU) g_mask[src] = 1;
}

// inv-sqrt + compact + bucket allocation with WARP-AGGREGATED atomics.
__global__ void k_inv_compact() {
    int i = blockIdx.x * 256 + threadIdx.x;
    int lane = threadIdx.x & 31;
    bool inb = (i < NN);
    int d = inb ? g_deg[i] : 0;
    if (inb) g_inv[i] = rsqrtf((float)d + 1.0f);
    bool active = inb && g_mask[i];
    unsigned ballot = __ballot_sync(0xFFFFFFFFu, active);
    int total = __popc(ballot);
    if (total == 0) return;
    int myidx = __popc(ballot & ((1u << lane) - 1));
    int dv = active ? d : 0;
    // warp inclusive scan of dv
    int v = dv;
    #pragma unroll
    for (int o = 1; o < 32; o <<= 1) {
        int t = __shfl_up_sync(0xFFFFFFFFu, v, o);
        if (lane >= o) v += t;
    }
    int excl = v - dv;
    int wsum = __shfl_sync(0xFFFFFFFFu, v, 31);
    int baseCnt = 0, baseOff = 0;
    if (lane == 0) {
        baseCnt = atomicAdd(&g_cnt, total);
        baseOff = atomicAdd(&g_total, wsum);
    }
    baseCnt = __shfl_sync(0xFFFFFFFFu, baseCnt, 0);
    baseOff = __shfl_sync(0xFFFFFFFFu, baseOff, 0);
    if (active) {
        g_list[baseCnt + myidx] = i;
        g_off[i] = baseOff + excl;
    }
}

// fill only buckets whose dst is in S (~1/3 of edges)
__global__ void k_fill(const void* __restrict__ eS, const void* __restrict__ eD,
                       long long dOff) {
    int e = blockIdx.x * 256 + threadIdx.x;
    if (e >= EE) return;
    int dst = edge_at(eD, dOff + e);
    if ((unsigned)dst >= NN || !g_mask[dst]) return;
    int src = edge_at(eS, e);
    if ((unsigned)src >= NN) return;
    int pos = g_off[dst] + atomicAdd(&g_cur[dst], 1);
    if ((unsigned)pos < EE) g_csr[pos] = src;
}

// x -> bf16 copy (halves agg1 gather bytes). grid = NN*FF/4 threads.
__global__ void k_tobf16(const float* __restrict__ x) {
    long long i = (long long)blockIdx.x * 256 + threadIdx.x;
    float4 v = ((const float4*)x)[i];
    __nv_bfloat162 a = __floats2bfloat162_rn(v.x, v.y);
    __nv_bfloat162 b = __floats2bfloat162_rn(v.z, v.w);
    uint2 u;
    u.x = *(unsigned*)&a;
    u.y = *(unsigned*)&b;
    ((uint2*)g_Xh)[i] = u;
}

// ---------------------------------------------------------------------------
// Layer-1 aggregation: warp per compact row; bf16 gathers, fp32 accum,
// fp32 self-term. Unrolled x4 for MLP.
__device__ __forceinline__ void bf16_fma(float4& acc, float c, uint2 u) {
    float2 f0 = __bfloat1622float2(*(__nv_bfloat162*)&u.x);
    float2 f1 = __bfloat1622float2(*(__nv_bfloat162*)&u.y);
    acc.x += c * f0.x; acc.y += c * f0.y;
    acc.z += c * f1.x; acc.w += c * f1.y;
}

__global__ void k_agg1(const float* __restrict__ x) {
    int w = (blockIdx.x * 256 + threadIdx.x) >> 5;
    int lane = threadIdx.x & 31;
    if (w >= g_cnt) return;
    int row = g_list[w];
    float invr = g_inv[row];
    float4 acc = ((const float4*)(x + (long long)row * FF))[lane];
    float s = invr * invr;
    acc.x *= s; acc.y *= s; acc.z *= s; acc.w *= s;
    int beg = g_off[row], end = beg + g_deg[row];
    int j = beg;
    for (; j + 4 <= end; j += 4) {
        int s0 = g_csr[j], s1 = g_csr[j + 1], s2 = g_csr[j + 2], s3 = g_csr[j + 3];
        float c0 = g_inv[s0] * invr, c1 = g_inv[s1] * invr;
        float c2 = g_inv[s2] * invr, c3 = g_inv[s3] * invr;
        uint2 u0 = *(const uint2*)(g_Xh + (long long)s0 * FF + lane * 4);
        uint2 u1 = *(const uint2*)(g_Xh + (long long)s1 * FF + lane * 4);
        uint2 u2 = *(const uint2*)(g_Xh + (long long)s2 * FF + lane * 4);
        uint2 u3 = *(const uint2*)(g_Xh + (long long)s3 * FF + lane * 4);
        bf16_fma(acc, c0, u0); bf16_fma(acc, c1, u1);
        bf16_fma(acc, c2, u2); bf16_fma(acc, c3, u3);
    }
    for (; j < end; j++) {
        int src = g_csr[j];
        float c = g_inv[src] * invr;
        uint2 u = *(const uint2*)(g_Xh + (long long)src * FF + lane * 4);
        bf16_fma(acc, c, u);
    }
    ((float4*)(g_A + (long long)row * FF))[lane] = acc;
}

// Layer-2 aggregation: warp per dst row < UU; fp32 (tiny).
__global__ void k_agg2() {
    int w = (blockIdx.x * 256 + threadIdx.x) >> 5;
    int lane = threadIdx.x & 31;
    if (w >= UU) return;
    int row = w;
    float invr = g_inv[row];
    float4 acc = ((const float4*)(g_H + (long long)row * FF))[lane];
    float s = invr * invr;
    acc.x *= s; acc.y *= s; acc.z *= s; acc.w *= s;
    int beg = g_off[row], end = beg + g_deg[row];
    int j = beg;
    for (; j + 2 <= end; j += 2) {
        int s0 = g_csr[j], s1 = g_csr[j + 1];
        float c0 = g_inv[s0] * invr, c1 = g_inv[s1] * invr;
        float4 v0 = ((const float4*)(g_H + (long long)s0 * FF))[lane];
        float4 v1 = ((const float4*)(g_H + (long long)s1 * FF))[lane];
        acc.x += c0 * v0.x + c1 * v1.x;
        acc.y += c0 * v0.y + c1 * v1.y;
        acc.z += c0 * v0.z + c1 * v1.z;
        acc.w += c0 * v0.w + c1 * v1.w;
    }
    for (; j < end; j++) {
        int src = g_csr[j];
        float c = g_inv[src] * invr;
        float4 v = ((const float4*)(g_H + (long long)src * FF))[lane];
        acc.x += c * v.x; acc.y += c * v.y; acc.z += c * v.z; acc.w += c * v.w;
    }
    ((float4*)(g_A + (long long)row * FF))[lane] = acc;
}

// ---------------------------------------------------------------------------
// Fused GEMM + bias + ELU, reading g_A by SYMBOL.
__global__ void k_gemm_fused(const float* __restrict__ W, const float* __restrict__ bias,
                             float* __restrict__ outp, int layer) {
    __shared__ float Ws[32 * 128];
    __shared__ float XsT[32 * 68];
    __shared__ int   rlist[64];
    __shared__ int   s_n;

    int tid = threadIdx.x;
    if (tid == 0) s_n = (layer == 1) ? g_cnt : UU;
    __syncthreads();
    int n = s_n;
    int base = blockIdx.x * 64;
    if (base >= n) return;

    if (tid < 64) {
        int gr = base + tid;
        rlist[tid] = (gr < n) ? ((layer == 1) ? g_list[gr] : gr) : -1;
    }
    float* O = (layer == 1) ? g_H : outp;

    int tx = tid & 15, ty = tid >> 4;
    float acc[4][8];
    #pragma unroll
    for (int i = 0; i < 4; i++)
        #pragma unroll
        for (int j = 0; j < 8; j++) acc[i][j] = 0.0f;
    __syncthreads();

    for (int kc = 0; kc < 128; kc += 32) {
        #pragma unroll 4
        for (int idx = tid; idx < 4096; idx += 256)
            Ws[idx] = W[(kc + (idx >> 7)) * 128 + (idx & 127)];
        #pragma unroll 4
        for (int idx = tid; idx < 2048; idx += 256) {
            int r = idx >> 5, c = idx & 31;
            int grow = rlist[r];
            XsT[c * 68 + r] = (grow >= 0) ? g_A[(long long)grow * FF + kc + c] : 0.0f;
        }
        __syncthreads();

        #pragma unroll
        for (int k = 0; k < 32; k++) {
            float4 a  = *(const float4*)&XsT[k * 68 + ty * 4];
            float4 b0 = *(const float4*)&Ws[k * 128 + tx * 4];
            float4 b1 = *(const float4*)&Ws[k * 128 + 64 + tx * 4];
            float av[4] = {a.x, a.y, a.z, a.w};
            float bv[8] = {b0.x, b0.y, b0.z, b0.w, b1.x, b1.y, b1.z, b1.w};
            #pragma unroll
            for (int i = 0; i < 4; i++)
                #pragma unroll
                for (int j = 0; j < 8; j++) acc[i][j] += av[i] * bv[j];
        }
        __syncthreads();
    }

    float bj[8];
    #pragma unroll
    for (int q = 0; q < 4; q++) {
        bj[q]     = __ldg(&bias[tx * 4 + q]);
        bj[4 + q] = __ldg(&bias[64 + tx * 4 + q]);
    }

    #pragma unroll
    for (int i = 0; i < 4; i++) {
        int gr = base + ty * 4 + i;
        if (gr < n) {
            int grow = rlist[ty * 4 + i];
            float* o = O + (long long)grow * FF;
            float r0[4], r1[4];
            #pragma unroll
            for (int q = 0; q < 4; q++) {
                float v = acc[i][q] + bj[q];
                r0[q] = (v > 0.0f) ? v : expm1f(v);
                v = acc[i][4 + q] + bj[4 + q];
                r1[q] = (v > 0.0f) ? v : expm1f(v);
            }
            *(float4*)&o[tx * 4]      = *(float4*)&r0[0];
            *(float4*)&o[64 + tx * 4] = *(float4*)&r1[0];
        }
    }
}

__global__ void k_copy_tail(const float* __restrict__ x, float* __restrict__ out) {
    long long idx = (long long)blockIdx.x * 256 + threadIdx.x;  // (NN-UU)*FF/4
    long long o = (long long)UU * FF / 4 + idx;
    ((float4*)out)[o] = ((const float4*)x)[o];
}

// ---------------------------------------------------------------------------
extern "C" void kernel_launch(void* const* d_in, const int* in_sizes, int n_in,
                              void* d_out, int out_size) {
    const float *x = 0, *W1 = 0, *b1 = 0, *W2 = 0, *b2 = 0;
    const void *eA = 0, *eB = 0;
    long long dOff = 0;
    for (int i = 0; i < n_in; i++) {
        long long s = in_sizes[i];
        if (s == (long long)NN * FF)      x = (const float*)d_in[i];
        else if (s == 2LL * EE)           eA = d_in[i];
        else if (s == (long long)EE)     { if (!eA) eA = d_in[i]; else eB = d_in[i]; }
        else if (s == FF * FF)           { if (!W1) W1 = (const float*)d_in[i];
                                           else     W2 = (const float*)d_in[i]; }
        else if (s == FF)                { if (!b1) b1 = (const float*)d_in[i];
                                           else     b2 = (const float*)d_in[i]; }
    }
    if (!eB) { eB = eA; dOff = EE; }
    float* out = (float*)d_out;

    const int egrid = (EE + 255) / 256;
    const int ngrid = (NN + 255) / 256;

    // setup + CSR (scan-free, masked buckets only)
    k_init<<<DETECT_N / 256, 256>>>((const int*)eA);
    k_tobf16<<<(NN * FF / 4) / 256, 256>>>(x);
    k_deg_mask<<<egrid, 256>>>(eA, eB, dOff);
    k_inv_compact<<<ngrid, 256>>>();
    k_fill<<<egrid, 256>>>(eA, eB, dOff);

    // layer 1: bf16 gather-aggregate over S, fused GEMM+bias+ELU -> g_H
    k_agg1<<<(NN * 32 + 255) / 256, 256>>>(x);
    k_gemm_fused<<<(NN + 63) / 64, 256>>>(W1, b1, out, 1);

    // layer 2: gather-aggregate h over [0,UU), fused GEMM -> out head
    k_agg2<<<(UU * 32 + 255) / 256, 256>>>();
    k_gemm_fused<<<(UU + 63) / 64, 256>>>(W2, b2, out, 2);

    // passthrough rows [U, N)
    k_copy_tail<<<((NN - UU) * FF / 4 + 255) / 256, 256>>>(x, out);
}